// round 14
// baseline (speedup 1.0000x reference)
#include <cuda_runtime.h>
#include <cuda_fp16.h>
#include <cstdint>

#define BB 16
#define C1 512
#define C2 1024
#define CTOT 1536
#define HW 4096
#define HW2 1024
#define OUTC 256
#define PP 2048
#define NPIX 65536

// ---------------- device scratch ----------------
__device__ __align__(16) __half g_pool[(size_t)BB * CTOT * HW];   // [b][c][hw]
__device__ __align__(16) __half g_Wh[OUTC * CTOT];                // [o][c]
__device__ __align__(16) __half g_Ch[PP * OUTC];                  // [p][c]
__device__ __align__(16) __half g_embh[(size_t)NPIX * OUTC];      // [pixel][o]
__device__ float g_en[NPIX];
__device__ float g_cn[PP];

// ---------------- asm helpers ----------------
__device__ __forceinline__ uint32_t smem_u32(const void* p) {
    uint32_t a;
    asm("{ .reg .u64 t; cvta.to.shared.u64 t, %1; cvt.u32.u64 %0, t; }" : "=r"(a) : "l"(p));
    return a;
}
__device__ __forceinline__ void mma16816(float& c0, float& c1, float& c2, float& c3,
                                         uint32_t a0, uint32_t a1, uint32_t a2, uint32_t a3,
                                         uint32_t b0, uint32_t b1) {
    asm volatile(
        "mma.sync.aligned.m16n8k16.row.col.f32.f16.f16.f32 "
        "{%0,%1,%2,%3}, {%4,%5,%6,%7}, {%8,%9}, {%0,%1,%2,%3};"
        : "+f"(c0), "+f"(c1), "+f"(c2), "+f"(c3)
        : "r"(a0), "r"(a1), "r"(a2), "r"(a3), "r"(b0), "r"(b1));
}
__device__ __forceinline__ void ldsm4(uint32_t* d, uint32_t addr) {
    asm volatile("ldmatrix.sync.aligned.m8n8.x4.shared.b16 {%0,%1,%2,%3}, [%4];"
                 : "=r"(d[0]), "=r"(d[1]), "=r"(d[2]), "=r"(d[3]) : "r"(addr));
}
__device__ __forceinline__ void ldsm4t(uint32_t* d, uint32_t addr) {
    asm volatile("ldmatrix.sync.aligned.m8n8.x4.trans.shared.b16 {%0,%1,%2,%3}, [%4];"
                 : "=r"(d[0]), "=r"(d[1]), "=r"(d[2]), "=r"(d[3]) : "r"(addr));
}
__device__ __forceinline__ void cp16(uint32_t dst, const void* src) {
    asm volatile("cp.async.cg.shared.global [%0], [%1], 16;" :: "r"(dst), "l"(src));
}
#define CP_COMMIT() asm volatile("cp.async.commit_group;" ::: "memory")
#define CP_WAIT0()  asm volatile("cp.async.wait_group 0;" ::: "memory")

// branch-free top-3 sorted insert (t0 <= t1 <= t2)
__device__ __forceinline__ void top3_insert(float v, float& t0, float& t1, float& t2) {
    float b0 = fmaxf(v, t0);
    t0 = fminf(v, t0);
    float b1 = fmaxf(b0, t1);
    t1 = fminf(b0, t1);
    t2 = fminf(b1, t2);
}

__device__ __forceinline__ void lin_taps(int i, int& j0, int& j1, float& w1) {
    float xf = 0.5f * (float)i - 0.25f;
    float fl = floorf(xf);
    int j = (int)fl;
    w1 = xf - fl;
    j0 = j < 0 ? 0 : j;
    j1 = (j + 1 > 31) ? 31 : (j + 1);
}

// ============================================================
// Kernel 1: fused pools, SEPARABLE 3x3.
// p1 blocks: horizontal pass then vertical pass on 64x64.
// p2 blocks: separable pool on 32x32, then bilinear 32->64 with
// hoisted x-taps (x fixed per thread).
// ============================================================
__global__ void pools_kernel(const float* __restrict__ p1, const float* __restrict__ p2) {
    __shared__ float buf[2 * HW];   // 32 KB
    int bid = blockIdx.x;
    int t = threadIdx.x;
    if (bid < BB * C1) {
        float* s = buf;
        float* h = buf + HW;
        const float* in = p1 + (size_t)bid * HW;
        int b = bid / C1, c = bid - b * C1;
        __half* out = g_pool + ((size_t)b * CTOT + c) * HW;
        #pragma unroll
        for (int k = 0; k < 16; ++k) s[t + 256 * k] = in[t + 256 * k];
        __syncthreads();
        // horizontal pass: h = s[x-1]+s[x]+s[x+1] (clamped to zero pad)
        #pragma unroll
        for (int k = 0; k < 16; ++k) {
            int i = t + 256 * k;
            int x = i & 63;
            float v = s[i];
            if (x > 0)  v += s[i - 1];
            if (x < 63) v += s[i + 1];
            h[i] = v;
        }
        __syncthreads();
        // vertical pass
        #pragma unroll
        for (int k = 0; k < 16; ++k) {
            int i = t + 256 * k;
            float v = h[i];
            if (i >= 64)        v += h[i - 64];
            if (i < HW - 64)    v += h[i + 64];
            out[i] = __float2half(v * (1.f / 9.f));
        }
    } else {
        int plane = bid - BB * C1;
        float* s = buf;
        float* h = buf + HW2;
        float* q = buf + 2 * HW2;
        const float* in = p2 + (size_t)plane * HW2;
        int b = plane / C2, c = plane - b * C2;
        __half* out = g_pool + ((size_t)b * CTOT + C1 + c) * HW;
        #pragma unroll
        for (int k = 0; k < 4; ++k) s[t + 256 * k] = in[t + 256 * k];
        __syncthreads();
        #pragma unroll
        for (int k = 0; k < 4; ++k) {
            int i = t + 256 * k;
            int x = i & 31;
            float v = s[i];
            if (x > 0)  v += s[i - 1];
            if (x < 31) v += s[i + 1];
            h[i] = v;
        }
        __syncthreads();
        #pragma unroll
        for (int k = 0; k < 4; ++k) {
            int i = t + 256 * k;
            float v = h[i];
            if (i >= 32)          v += h[i - 32];
            if (i < HW2 - 32)     v += h[i + 32];
            q[i] = v * (1.f / 9.f);
        }
        __syncthreads();
        // bilinear 32->64: thread owns fixed x = t&63, rows y = (t>>6) + 4k
        int x = t & 63, yb = t >> 6;
        int x0, x1; float wx;
        lin_taps(x, x0, x1, wx);
        float wxc = 1.f - wx;
        #pragma unroll
        for (int k = 0; k < 16; ++k) {
            int y = yb + 4 * k;
            int y0, y1; float wy;
            lin_taps(y, y0, y1, wy);
            float v0 = q[y0 * 32 + x0] * wxc + q[y0 * 32 + x1] * wx;
            float v1 = q[y1 * 32 + x0] * wxc + q[y1 * 32 + x1] * wx;
            out[y * 64 + x] = __float2half(v0 * (1.f - wy) + v1 * wy);
        }
    }
}

// ============================================================
// Kernel 2: fused conversions (W -> fp16; centroids -> fp16 + ||c||^2)
// ============================================================
__global__ void conv_kernel(const float* __restrict__ w, const float* __restrict__ cents) {
    int bid = blockIdx.x;
    if (bid < 1536) {
        int i = bid * 256 + threadIdx.x;
        g_Wh[i] = __float2half(w[i]);
    } else {
        int warp = (bid - 1536) * 8 + (threadIdx.x >> 5);
        int lane = threadIdx.x & 31;
        float s = 0.f;
        for (int k = lane; k < OUTC; k += 32) {
            __half h = __float2half(cents[(size_t)warp * OUTC + k]);
            g_Ch[(size_t)warp * OUTC + k] = h;
            float f = __half2float(h);
            s = fmaf(f, f, s);
        }
        #pragma unroll
        for (int off = 16; off; off >>= 1) s += __shfl_xor_sync(0xffffffffu, s, off);
        if (lane == 0) g_cn[warp] = s;
    }
}

// ============================================================
// Kernel 3: projection GEMM (R11 config, unchanged).
// Block 128m x 256n, 8 warps (2m x 4n), warp 64x64, K-step 64.
// ============================================================
#define G1_LDA 136
#define G1_ABUF 17408
#define G1_LDB 72
#define G1_BBUF 36864
#define G1_BS_OFF 34816
#define G1_BIAS_OFF 108544
#define G1_EN_OFF 109568
#define G1_SMEM (G1_EN_OFF + 512)

__global__ void __launch_bounds__(256) gemm1_kernel(const float* __restrict__ bias) {
    extern __shared__ char smem[];
    const uint32_t sb = smem_u32(smem);
    float* bias_s = (float*)(smem + G1_BIAS_OFF);
    float* en_s = (float*)(smem + G1_EN_OFF);

    const int t = threadIdx.x;
    const int w = t >> 5, lane = t & 31;
    const int warpm = w >> 2, warpn = w & 3;
    const int g = lane >> 2, tig = lane & 3;
    const int j = lane >> 3, r = lane & 7;
    const int m0 = blockIdx.x * 128;
    const int b = m0 >> 12, hw0 = m0 & 4095;

    bias_s[t] = bias[t];
    if (t < 128) en_s[t] = 0.f;

    const int ak = t >> 4, am8 = (t & 15) * 8;
    const int bn = t >> 3, bkq8 = (t & 7) * 8;
    const __half* apsrc = g_pool + ((size_t)b * CTOT + ak) * HW + hw0 + am8;
    const __half* bpsrc = g_Wh + (size_t)bn * CTOT + bkq8;
    const uint32_t adst = sb + (ak * G1_LDA + am8) * 2;
    const uint32_t bdst = sb + G1_BS_OFF + (bn * G1_LDB + bkq8) * 2;

    const uint32_t abase = sb + (((j >> 1) * 8 + r) * G1_LDA + warpm * 64 + (j & 1) * 8) * 2;
    const uint32_t bbase = sb + G1_BS_OFF +
                           ((warpn * 64 + (j & 1) * 8 + r) * G1_LDB + (j >> 1) * 8) * 2;

    float acc[4][8][4];
    #pragma unroll
    for (int mt = 0; mt < 4; ++mt)
        #pragma unroll
        for (int nt = 0; nt < 8; ++nt)
            #pragma unroll
            for (int q = 0; q < 4; ++q) acc[mt][nt][q] = 0.f;

    #pragma unroll
    for (int i = 0; i < 4; ++i)
        cp16(adst + i * 16 * G1_LDA * 2, apsrc + (size_t)(16 * i) * HW);
    #pragma unroll
    for (int i = 0; i < 8; ++i)
        cp16(bdst + i * 32 * G1_LDB * 2, bpsrc + (size_t)(32 * i) * CTOT);
    CP_COMMIT();

    const int NT = CTOT / 64;  // 24
    for (int kt = 0; kt < NT; ++kt) {
        CP_WAIT0();
        __syncthreads();
        if (kt + 1 < NT) {
            int k0 = (kt + 1) * 64;
            uint32_t ao = ((kt + 1) & 1) * G1_ABUF;
            uint32_t bo = ((kt + 1) & 1) * G1_BBUF;
            #pragma unroll
            for (int i = 0; i < 4; ++i)
                cp16(adst + ao + i * 16 * G1_LDA * 2, apsrc + (size_t)(k0 + 16 * i) * HW);
            #pragma unroll
            for (int i = 0; i < 8; ++i)
                cp16(bdst + bo + i * 32 * G1_LDB * 2, bpsrc + (size_t)(32 * i) * CTOT + k0);
            CP_COMMIT();
        }
        uint32_t aab = abase + (kt & 1) * G1_ABUF;
        uint32_t bbb = bbase + (kt & 1) * G1_BBUF;
        #pragma unroll
        for (int ks = 0; ks < 4; ++ks) {
            int ks16 = ks * 16;
            uint32_t a[4][4], bf[4][4];
            #pragma unroll
            for (int mt = 0; mt < 4; ++mt)
                ldsm4t(a[mt], aab + (ks16 * G1_LDA + mt * 16) * 2);
            #pragma unroll
            for (int ng = 0; ng < 4; ++ng)
                ldsm4(bf[ng], bbb + (ng * 16 * G1_LDB + ks16) * 2);
            #pragma unroll
            for (int mt = 0; mt < 4; ++mt)
                #pragma unroll
                for (int ng = 0; ng < 4; ++ng) {
                    mma16816(acc[mt][2*ng][0], acc[mt][2*ng][1], acc[mt][2*ng][2], acc[mt][2*ng][3],
                             a[mt][0], a[mt][1], a[mt][2], a[mt][3], bf[ng][0], bf[ng][2]);
                    mma16816(acc[mt][2*ng+1][0], acc[mt][2*ng+1][1], acc[mt][2*ng+1][2], acc[mt][2*ng+1][3],
                             a[mt][0], a[mt][1], a[mt][2], a[mt][3], bf[ng][1], bf[ng][3]);
                }
        }
    }
    __syncthreads();

    #pragma unroll
    for (int mt = 0; mt < 4; ++mt) {
        int row0 = warpm * 64 + mt * 16 + g;
        float en0 = 0.f, en1 = 0.f;
        #pragma unroll
        for (int nt = 0; nt < 8; ++nt) {
            int col = warpn * 64 + nt * 8 + tig * 2;
            float f0 = acc[mt][nt][0] + bias_s[col];
            float f1 = acc[mt][nt][1] + bias_s[col + 1];
            __half2 h01 = __floats2half2_rn(f0, f1);
            *(uint32_t*)(g_embh + (size_t)(m0 + row0) * OUTC + col) = *(uint32_t*)&h01;
            float q0 = __half2float(__low2half(h01)), q1 = __half2float(__high2half(h01));
            en0 = fmaf(q0, q0, fmaf(q1, q1, en0));

            float f2 = acc[mt][nt][2] + bias_s[col];
            float f3 = acc[mt][nt][3] + bias_s[col + 1];
            __half2 h23 = __floats2half2_rn(f2, f3);
            *(uint32_t*)(g_embh + (size_t)(m0 + row0 + 8) * OUTC + col) = *(uint32_t*)&h23;
            float q2 = __half2float(__low2half(h23)), q3 = __half2float(__high2half(h23));
            en1 = fmaf(q2, q2, fmaf(q3, q3, en1));
        }
        en0 += __shfl_xor_sync(0xffffffffu, en0, 1);
        en0 += __shfl_xor_sync(0xffffffffu, en0, 2);
        en1 += __shfl_xor_sync(0xffffffffu, en1, 1);
        en1 += __shfl_xor_sync(0xffffffffu, en1, 2);
        if (tig == 0) {
            atomicAdd(&en_s[warpm * 64 + mt * 16 + g], en0);
            atomicAdd(&en_s[warpm * 64 + mt * 16 + 8 + g], en1);
        }
    }
    __syncthreads();
    if (t < 128) g_en[m0 + t] = en_s[t];
}

// ============================================================
// Kernel 4: distance GEMM + top-3 + score (R10/R11-best, unchanged).
// ============================================================
#define G2_LDA 264
#define G2_LDB 72
#define G2_AS_BYTES (128 * G2_LDA * 2)
#define G2_BBUF (128 * G2_LDB * 2)
#define G2_CN_OFF (G2_AS_BYTES + 2 * G2_BBUF)
#define G2_SMEM (G2_CN_OFF + 8192)

__global__ void __launch_bounds__(256) gemm2_kernel(float* __restrict__ out) {
    extern __shared__ char smem[];
    const uint32_t sb = smem_u32(smem);
    __half* As = (__half*)smem;
    float* cn_s = (float*)(smem + G2_CN_OFF);

    const int t = threadIdx.x;
    const int w = t >> 5, lane = t & 31;
    const int warpm = w >> 1, warpn = w & 1;
    const int g = lane >> 2, tig = lane & 3;
    const int j = lane >> 3, r = lane & 7;
    const int m0 = blockIdx.x * 128;

    #pragma unroll
    for (int i = 0; i < 8; ++i) cn_s[t + 256 * i] = g_cn[t + 256 * i];

    #pragma unroll
    for (int i = 0; i < 16; ++i) {
        int idx = t + 256 * i;
        int row = idx >> 5, q = idx & 31;
        uint4 v = *(const uint4*)(g_embh + (size_t)(m0 + row) * OUTC + q * 8);
        *(uint4*)(As + row * G2_LDA + q * 8) = v;
    }

    const uint32_t bs0 = sb + G2_AS_BYTES;

    const uint32_t abase = sb + ((warpm * 32 + (j & 1) * 8 + r) * G2_LDA + (j >> 1) * 8) * 2;
    const uint32_t bbase = bs0 + ((warpn * 64 + (j & 1) * 8 + r) * G2_LDB + (j >> 1) * 8) * 2;

    float t3[4][3];
    #pragma unroll
    for (int s = 0; s < 4; ++s) { t3[s][0] = 3.4e38f; t3[s][1] = 3.4e38f; t3[s][2] = 3.4e38f; }

    float acc[2][8][4];

    #pragma unroll
    for (int i = 0; i < 4; ++i) {
        int idx = t + 256 * i;
        int row = idx >> 3, q8 = (idx & 7) * 8;
        cp16(bs0 + (row * G2_LDB + q8) * 2, g_Ch + (size_t)row * OUTC + q8);
    }
    CP_COMMIT();
    __syncthreads();

    for (int gi = 0; gi < 64; ++gi) {
        int cur = gi & 1;
        int chunk = gi >> 2, sl = gi & 3;

        CP_WAIT0();
        __syncthreads();
        if (gi + 1 < 64) {
            int nchunk = (gi + 1) >> 2, nsl = (gi + 1) & 3;
            uint32_t bo = ((gi + 1) & 1) * G2_BBUF;
            #pragma unroll
            for (int i = 0; i < 4; ++i) {
                int idx = t + 256 * i;
                int row = idx >> 3, q8 = (idx & 7) * 8;
                cp16(bs0 + bo + (row * G2_LDB + q8) * 2,
                     g_Ch + (size_t)(nchunk * 128 + row) * OUTC + nsl * 64 + q8);
            }
            CP_COMMIT();
        }

        if (sl == 0) {
            #pragma unroll
            for (int mt = 0; mt < 2; ++mt)
                #pragma unroll
                for (int nt = 0; nt < 8; ++nt)
                    #pragma unroll
                    for (int q = 0; q < 4; ++q) acc[mt][nt][q] = 0.f;
        }

        uint32_t bbb = bbase + cur * G2_BBUF;
        #pragma unroll
        for (int ks = 0; ks < 4; ++ks) {
            int ks16 = ks * 16;
            int kk = sl * 64 + ks16;
            uint32_t a[2][4], bf[4][4];
            #pragma unroll
            for (int mt = 0; mt < 2; ++mt)
                ldsm4(a[mt], abase + (mt * 16 * G2_LDA + kk) * 2);
            #pragma unroll
            for (int ng = 0; ng < 4; ++ng)
                ldsm4(bf[ng], bbb + (ng * 16 * G2_LDB + ks16) * 2);
            #pragma unroll
            for (int mt = 0; mt < 2; ++mt)
                #pragma unroll
                for (int ng = 0; ng < 4; ++ng) {
                    mma16816(acc[mt][2*ng][0], acc[mt][2*ng][1], acc[mt][2*ng][2], acc[mt][2*ng][3],
                             a[mt][0], a[mt][1], a[mt][2], a[mt][3], bf[ng][0], bf[ng][2]);
                    mma16816(acc[mt][2*ng+1][0], acc[mt][2*ng+1][1], acc[mt][2*ng+1][2], acc[mt][2*ng+1][3],
                             a[mt][0], a[mt][1], a[mt][2], a[mt][3], bf[ng][1], bf[ng][3]);
                }
        }

        if (sl == 3) {
            #pragma unroll
            for (int mt = 0; mt < 2; ++mt) {
                #pragma unroll
                for (int nt = 0; nt < 8; ++nt) {
                    int col = chunk * 128 + warpn * 64 + nt * 8 + tig * 2;
                    float cn0 = cn_s[col], cn1 = cn_s[col + 1];
                    #pragma unroll
                    for (int hi = 0; hi < 2; ++hi) {
                        int s = mt * 2 + hi;
                        float v0 = cn0 - 2.f * acc[mt][nt][hi * 2 + 0];
                        float v1 = cn1 - 2.f * acc[mt][nt][hi * 2 + 1];
                        top3_insert(v0, t3[s][0], t3[s][1], t3[s][2]);
                        top3_insert(v1, t3[s][0], t3[s][1], t3[s][2]);
                    }
                }
            }
        }
    }
    __syncthreads();

    float* mrg = (float*)(smem + G2_AS_BYTES);
    #pragma unroll
    for (int mt = 0; mt < 2; ++mt)
        #pragma unroll
        for (int hi = 0; hi < 2; ++hi) {
            int row = warpm * 32 + mt * 16 + hi * 8 + g;
            int slot = warpn * 4 + tig;
            float* d = mrg + (row * 8 + slot) * 3;
            d[0] = t3[mt * 2 + hi][0];
            d[1] = t3[mt * 2 + hi][1];
            d[2] = t3[mt * 2 + hi][2];
        }
    __syncthreads();

    if (t < 128) {
        float b0 = 3.4e38f, b1 = 3.4e38f, b2 = 3.4e38f;
        const float* src = mrg + t * 24;
        #pragma unroll
        for (int q = 0; q < 24; ++q)
            top3_insert(src[q], b0, b1, b2);
        float en = g_en[m0 + t];
        float d0 = sqrtf(fmaxf(en + b0, 0.f));
        float d1 = sqrtf(fmaxf(en + b1, 0.f));
        float d2 = sqrtf(fmaxf(en + b2, 0.f));
        out[m0 + t] = d0 / (1.f + expf(d0 - d1) + expf(d0 - d2));
    }
}

// ============================================================
// Launcher
// ============================================================
extern "C" void kernel_launch(void* const* d_in, const int* in_sizes, int n_in,
                              void* d_out, int out_size) {
    const float* p1 = (const float*)d_in[0];
    const float* p2 = (const float*)d_in[1];
    const float* pw = (const float*)d_in[2];
    const float* pb = (const float*)d_in[3];
    const float* ce = (const float*)d_in[4];
    float* out = (float*)d_out;
    (void)in_sizes; (void)n_in; (void)out_size;

    cudaFuncSetAttribute(gemm1_kernel, cudaFuncAttributeMaxDynamicSharedMemorySize, G1_SMEM);
    cudaFuncSetAttribute(gemm2_kernel, cudaFuncAttributeMaxDynamicSharedMemorySize, G2_SMEM);

    pools_kernel<<<BB * C1 + BB * C2, 256>>>(p1, p2);
    conv_kernel<<<1536 + 256, 256>>>(pw, ce);
    gemm1_kernel<<<NPIX / 128, 256, G1_SMEM>>>(pb);
    gemm2_kernel<<<NPIX / 128, 256, G2_SMEM>>>(out);
}

// round 15
// speedup vs baseline: 1.0912x; 1.0912x over previous
#include <cuda_runtime.h>
#include <cuda_fp16.h>
#include <cstdint>

#define BB 16
#define C1 512
#define C2 1024
#define CTOT 1536
#define HW 4096
#define HW2 1024
#define OUTC 256
#define PP 2048
#define NPIX 65536

// ---------------- device scratch ----------------
__device__ __align__(16) __half g_pool[(size_t)BB * CTOT * HW];   // [b][c][hw]
__device__ __align__(16) __half g_Wh[OUTC * CTOT];                // [o][c]
__device__ __align__(16) __half g_Ch[PP * OUTC];                  // [p][c]
__device__ __align__(16) __half g_embh[(size_t)NPIX * OUTC];      // [pixel][o]
__device__ float g_en[NPIX];
__device__ float g_cn[PP];

// ---------------- asm helpers ----------------
__device__ __forceinline__ uint32_t smem_u32(const void* p) {
    uint32_t a;
    asm("{ .reg .u64 t; cvta.to.shared.u64 t, %1; cvt.u32.u64 %0, t; }" : "=r"(a) : "l"(p));
    return a;
}
__device__ __forceinline__ void mma16816(float& c0, float& c1, float& c2, float& c3,
                                         uint32_t a0, uint32_t a1, uint32_t a2, uint32_t a3,
                                         uint32_t b0, uint32_t b1) {
    asm volatile(
        "mma.sync.aligned.m16n8k16.row.col.f32.f16.f16.f32 "
        "{%0,%1,%2,%3}, {%4,%5,%6,%7}, {%8,%9}, {%0,%1,%2,%3};"
        : "+f"(c0), "+f"(c1), "+f"(c2), "+f"(c3)
        : "r"(a0), "r"(a1), "r"(a2), "r"(a3), "r"(b0), "r"(b1));
}
__device__ __forceinline__ void ldsm4(uint32_t* d, uint32_t addr) {
    asm volatile("ldmatrix.sync.aligned.m8n8.x4.shared.b16 {%0,%1,%2,%3}, [%4];"
                 : "=r"(d[0]), "=r"(d[1]), "=r"(d[2]), "=r"(d[3]) : "r"(addr));
}
__device__ __forceinline__ void ldsm4t(uint32_t* d, uint32_t addr) {
    asm volatile("ldmatrix.sync.aligned.m8n8.x4.trans.shared.b16 {%0,%1,%2,%3}, [%4];"
                 : "=r"(d[0]), "=r"(d[1]), "=r"(d[2]), "=r"(d[3]) : "r"(addr));
}
__device__ __forceinline__ void cp16(uint32_t dst, const void* src) {
    asm volatile("cp.async.cg.shared.global [%0], [%1], 16;" :: "r"(dst), "l"(src));
}
#define CP_COMMIT() asm volatile("cp.async.commit_group;" ::: "memory")
#define CP_WAIT0()  asm volatile("cp.async.wait_group 0;" ::: "memory")

// branch-free top-3 sorted insert (t0 <= t1 <= t2)
__device__ __forceinline__ void top3_insert(float v, float& t0, float& t1, float& t2) {
    float b0 = fmaxf(v, t0);
    t0 = fminf(v, t0);
    float b1 = fmaxf(b0, t1);
    t1 = fminf(b0, t1);
    t2 = fminf(b1, t2);
}

__device__ __forceinline__ void lin_taps(int i, int& j0, int& j1, float& w1) {
    float xf = 0.5f * (float)i - 0.25f;
    float fl = floorf(xf);
    int j = (int)fl;
    w1 = xf - fl;
    j0 = j < 0 ? 0 : j;
    j1 = (j + 1 > 31) ? 31 : (j + 1);
}

// ============================================================
// Kernel 1: fused pools, SEPARABLE 3x3, float4-vectorized.
// p1 blocks: 64x64 pool. p2 blocks: 32x32 pool + bilinear 32->64.
// ============================================================
__global__ void pools_kernel(const float* __restrict__ p1, const float* __restrict__ p2) {
    __shared__ __align__(16) float buf[3 * HW2 > 2 * HW ? 3 * HW2 : 2 * HW];  // 32 KB
    const float inv9 = 1.f / 9.f;
    int bid = blockIdx.x;
    int t = threadIdx.x;
    if (bid < BB * C1) {
        float4* s4 = (float4*)buf;              // [1024]
        float4* h4 = (float4*)(buf + HW);       // [1024]
        const float4* in4 = (const float4*)(p1 + (size_t)bid * HW);
        int b = bid / C1, c = bid - b * C1;
        __half* out = g_pool + ((size_t)b * CTOT + c) * HW;
        #pragma unroll
        for (int k = 0; k < 4; ++k) s4[t + 256 * k] = in4[t + 256 * k];
        __syncthreads();
        // horizontal pass (zero pad)
        const float* sf = (const float*)s4;
        #pragma unroll
        for (int k = 0; k < 4; ++k) {
            int i = t + 256 * k;
            int xq = i & 15;
            float4 cv = s4[i];
            float L = (xq > 0)  ? sf[4 * i - 1] : 0.f;
            float R = (xq < 15) ? sf[4 * i + 4] : 0.f;
            float4 hv;
            hv.x = L + cv.x + cv.y;
            hv.y = cv.x + cv.y + cv.z;
            hv.z = cv.y + cv.z + cv.w;
            hv.w = cv.z + cv.w + R;
            h4[i] = hv;
        }
        __syncthreads();
        // vertical pass + /9 + fp16 store
        #pragma unroll
        for (int k = 0; k < 4; ++k) {
            int i = t + 256 * k;
            int row = i >> 4;
            float4 cv = h4[i];
            if (row > 0)  { float4 u = h4[i - 16]; cv.x += u.x; cv.y += u.y; cv.z += u.z; cv.w += u.w; }
            if (row < 63) { float4 d = h4[i + 16]; cv.x += d.x; cv.y += d.y; cv.z += d.z; cv.w += d.w; }
            __half2 ha = __floats2half2_rn(cv.x * inv9, cv.y * inv9);
            __half2 hb = __floats2half2_rn(cv.z * inv9, cv.w * inv9);
            *(uint2*)(out + 4 * i) = make_uint2(*(uint32_t*)&ha, *(uint32_t*)&hb);
        }
    } else {
        int plane = bid - BB * C1;
        float4* s4 = (float4*)buf;                    // [256]
        float4* h4 = (float4*)(buf + HW2);            // [256]
        float*  q  = buf + 2 * HW2;                   // [1024]
        float4* q4 = (float4*)q;
        const float4* in4 = (const float4*)(p2 + (size_t)plane * HW2);
        int b = plane / C2, c = plane - b * C2;
        __half* out = g_pool + ((size_t)b * CTOT + C1 + c) * HW;
        s4[t] = in4[t];
        __syncthreads();
        {
            const float* sf = (const float*)s4;
            int xq = t & 7;
            float4 cv = s4[t];
            float L = (xq > 0) ? sf[4 * t - 1] : 0.f;
            float R = (xq < 7) ? sf[4 * t + 4] : 0.f;
            float4 hv;
            hv.x = L + cv.x + cv.y;
            hv.y = cv.x + cv.y + cv.z;
            hv.z = cv.y + cv.z + cv.w;
            hv.w = cv.z + cv.w + R;
            h4[t] = hv;
        }
        __syncthreads();
        {
            int row = t >> 3;
            float4 cv = h4[t];
            if (row > 0)  { float4 u = h4[t - 8]; cv.x += u.x; cv.y += u.y; cv.z += u.z; cv.w += u.w; }
            if (row < 31) { float4 d = h4[t + 8]; cv.x += d.x; cv.y += d.y; cv.z += d.z; cv.w += d.w; }
            cv.x *= inv9; cv.y *= inv9; cv.z *= inv9; cv.w *= inv9;
            q4[t] = cv;
        }
        __syncthreads();
        // bilinear 32->64: 512 groups of 8 out px; 2 iterations
        #pragma unroll
        for (int k = 0; k < 2; ++k) {
            int gidx = t + 256 * k;
            int y = gidx >> 3, xg = gidx & 7;
            int y0, y1; float wy;
            lin_taps(y, y0, y1, wy);
            float wyc = 1.f - wy;
            const float* r0 = q + y0 * 32 + xg * 4;
            const float* r1 = q + y1 * 32 + xg * 4;
            float4 a0 = *(const float4*)r0;
            float4 a1 = *(const float4*)r1;
            float l0 = (xg > 0) ? r0[-1] : a0.x;
            float l1 = (xg > 0) ? r1[-1] : a1.x;
            float rr0 = (xg < 7) ? r0[4] : a0.w;
            float rr1 = (xg < 7) ? r1[4] : a1.w;
            float e0[8], e1[8];
            e0[0] = 0.25f * l0  + 0.75f * a0.x;  e1[0] = 0.25f * l1  + 0.75f * a1.x;
            e0[1] = 0.75f * a0.x + 0.25f * a0.y; e1[1] = 0.75f * a1.x + 0.25f * a1.y;
            e0[2] = 0.25f * a0.x + 0.75f * a0.y; e1[2] = 0.25f * a1.x + 0.75f * a1.y;
            e0[3] = 0.75f * a0.y + 0.25f * a0.z; e1[3] = 0.75f * a1.y + 0.25f * a1.z;
            e0[4] = 0.25f * a0.y + 0.75f * a0.z; e1[4] = 0.25f * a1.y + 0.75f * a1.z;
            e0[5] = 0.75f * a0.z + 0.25f * a0.w; e1[5] = 0.75f * a1.z + 0.25f * a1.w;
            e0[6] = 0.25f * a0.z + 0.75f * a0.w; e1[6] = 0.25f * a1.z + 0.75f * a1.w;
            e0[7] = 0.75f * a0.w + 0.25f * rr0;  e1[7] = 0.75f * a1.w + 0.25f * rr1;
            uint32_t packed[4];
            #pragma unroll
            for (int p = 0; p < 4; ++p) {
                float o0 = e0[2 * p]     * wyc + e1[2 * p]     * wy;
                float o1 = e0[2 * p + 1] * wyc + e1[2 * p + 1] * wy;
                __half2 h = __floats2half2_rn(o0, o1);
                packed[p] = *(uint32_t*)&h;
            }
            *(uint4*)(out + y * 64 + xg * 8) = make_uint4(packed[0], packed[1], packed[2], packed[3]);
        }
    }
}

// ============================================================
// Kernel 2: fused conversions (W -> fp16; centroids -> fp16 + ||c||^2)
// ============================================================
__global__ void conv_kernel(const float* __restrict__ w, const float* __restrict__ cents) {
    int bid = blockIdx.x;
    if (bid < 1536) {
        int i = bid * 256 + threadIdx.x;
        g_Wh[i] = __float2half(w[i]);
    } else {
        int warp = (bid - 1536) * 8 + (threadIdx.x >> 5);
        int lane = threadIdx.x & 31;
        float s = 0.f;
        for (int k = lane; k < OUTC; k += 32) {
            __half h = __float2half(cents[(size_t)warp * OUTC + k]);
            g_Ch[(size_t)warp * OUTC + k] = h;
            float f = __half2float(h);
            s = fmaf(f, f, s);
        }
        #pragma unroll
        for (int off = 16; off; off >>= 1) s += __shfl_xor_sync(0xffffffffu, s, off);
        if (lane == 0) g_cn[warp] = s;
    }
}

// ============================================================
// Kernel 3: projection GEMM (R11/R14 config, unchanged).
// ============================================================
#define G1_LDA 136
#define G1_ABUF 17408
#define G1_LDB 72
#define G1_BBUF 36864
#define G1_BS_OFF 34816
#define G1_BIAS_OFF 108544
#define G1_EN_OFF 109568
#define G1_SMEM (G1_EN_OFF + 512)

__global__ void __launch_bounds__(256) gemm1_kernel(const float* __restrict__ bias) {
    extern __shared__ char smem[];
    const uint32_t sb = smem_u32(smem);
    float* bias_s = (float*)(smem + G1_BIAS_OFF);
    float* en_s = (float*)(smem + G1_EN_OFF);

    const int t = threadIdx.x;
    const int w = t >> 5, lane = t & 31;
    const int warpm = w >> 2, warpn = w & 3;
    const int g = lane >> 2, tig = lane & 3;
    const int j = lane >> 3, r = lane & 7;
    const int m0 = blockIdx.x * 128;
    const int b = m0 >> 12, hw0 = m0 & 4095;

    bias_s[t] = bias[t];
    if (t < 128) en_s[t] = 0.f;

    const int ak = t >> 4, am8 = (t & 15) * 8;
    const int bn = t >> 3, bkq8 = (t & 7) * 8;
    const __half* apsrc = g_pool + ((size_t)b * CTOT + ak) * HW + hw0 + am8;
    const __half* bpsrc = g_Wh + (size_t)bn * CTOT + bkq8;
    const uint32_t adst = sb + (ak * G1_LDA + am8) * 2;
    const uint32_t bdst = sb + G1_BS_OFF + (bn * G1_LDB + bkq8) * 2;

    const uint32_t abase = sb + (((j >> 1) * 8 + r) * G1_LDA + warpm * 64 + (j & 1) * 8) * 2;
    const uint32_t bbase = sb + G1_BS_OFF +
                           ((warpn * 64 + (j & 1) * 8 + r) * G1_LDB + (j >> 1) * 8) * 2;

    float acc[4][8][4];
    #pragma unroll
    for (int mt = 0; mt < 4; ++mt)
        #pragma unroll
        for (int nt = 0; nt < 8; ++nt)
            #pragma unroll
            for (int q = 0; q < 4; ++q) acc[mt][nt][q] = 0.f;

    #pragma unroll
    for (int i = 0; i < 4; ++i)
        cp16(adst + i * 16 * G1_LDA * 2, apsrc + (size_t)(16 * i) * HW);
    #pragma unroll
    for (int i = 0; i < 8; ++i)
        cp16(bdst + i * 32 * G1_LDB * 2, bpsrc + (size_t)(32 * i) * CTOT);
    CP_COMMIT();

    const int NT = CTOT / 64;  // 24
    for (int kt = 0; kt < NT; ++kt) {
        CP_WAIT0();
        __syncthreads();
        if (kt + 1 < NT) {
            int k0 = (kt + 1) * 64;
            uint32_t ao = ((kt + 1) & 1) * G1_ABUF;
            uint32_t bo = ((kt + 1) & 1) * G1_BBUF;
            #pragma unroll
            for (int i = 0; i < 4; ++i)
                cp16(adst + ao + i * 16 * G1_LDA * 2, apsrc + (size_t)(k0 + 16 * i) * HW);
            #pragma unroll
            for (int i = 0; i < 8; ++i)
                cp16(bdst + bo + i * 32 * G1_LDB * 2, bpsrc + (size_t)(32 * i) * CTOT + k0);
            CP_COMMIT();
        }
        uint32_t aab = abase + (kt & 1) * G1_ABUF;
        uint32_t bbb = bbase + (kt & 1) * G1_BBUF;
        #pragma unroll
        for (int ks = 0; ks < 4; ++ks) {
            int ks16 = ks * 16;
            uint32_t a[4][4], bf[4][4];
            #pragma unroll
            for (int mt = 0; mt < 4; ++mt)
                ldsm4t(a[mt], aab + (ks16 * G1_LDA + mt * 16) * 2);
            #pragma unroll
            for (int ng = 0; ng < 4; ++ng)
                ldsm4(bf[ng], bbb + (ng * 16 * G1_LDB + ks16) * 2);
            #pragma unroll
            for (int mt = 0; mt < 4; ++mt)
                #pragma unroll
                for (int ng = 0; ng < 4; ++ng) {
                    mma16816(acc[mt][2*ng][0], acc[mt][2*ng][1], acc[mt][2*ng][2], acc[mt][2*ng][3],
                             a[mt][0], a[mt][1], a[mt][2], a[mt][3], bf[ng][0], bf[ng][2]);
                    mma16816(acc[mt][2*ng+1][0], acc[mt][2*ng+1][1], acc[mt][2*ng+1][2], acc[mt][2*ng+1][3],
                             a[mt][0], a[mt][1], a[mt][2], a[mt][3], bf[ng][1], bf[ng][3]);
                }
        }
    }
    __syncthreads();

    #pragma unroll
    for (int mt = 0; mt < 4; ++mt) {
        int row0 = warpm * 64 + mt * 16 + g;
        float en0 = 0.f, en1 = 0.f;
        #pragma unroll
        for (int nt = 0; nt < 8; ++nt) {
            int col = warpn * 64 + nt * 8 + tig * 2;
            float f0 = acc[mt][nt][0] + bias_s[col];
            float f1 = acc[mt][nt][1] + bias_s[col + 1];
            __half2 h01 = __floats2half2_rn(f0, f1);
            *(uint32_t*)(g_embh + (size_t)(m0 + row0) * OUTC + col) = *(uint32_t*)&h01;
            float q0 = __half2float(__low2half(h01)), q1 = __half2float(__high2half(h01));
            en0 = fmaf(q0, q0, fmaf(q1, q1, en0));

            float f2 = acc[mt][nt][2] + bias_s[col];
            float f3 = acc[mt][nt][3] + bias_s[col + 1];
            __half2 h23 = __floats2half2_rn(f2, f3);
            *(uint32_t*)(g_embh + (size_t)(m0 + row0 + 8) * OUTC + col) = *(uint32_t*)&h23;
            float q2 = __half2float(__low2half(h23)), q3 = __half2float(__high2half(h23));
            en1 = fmaf(q2, q2, fmaf(q3, q3, en1));
        }
        en0 += __shfl_xor_sync(0xffffffffu, en0, 1);
        en0 += __shfl_xor_sync(0xffffffffu, en0, 2);
        en1 += __shfl_xor_sync(0xffffffffu, en1, 1);
        en1 += __shfl_xor_sync(0xffffffffu, en1, 2);
        if (tig == 0) {
            atomicAdd(&en_s[warpm * 64 + mt * 16 + g], en0);
            atomicAdd(&en_s[warpm * 64 + mt * 16 + 8 + g], en1);
        }
    }
    __syncthreads();
    if (t < 128) g_en[m0 + t] = en_s[t];
}

// ============================================================
// Kernel 4: distance GEMM + top-3 + score (R10/R14-best, unchanged).
// ============================================================
#define G2_LDA 264
#define G2_LDB 72
#define G2_AS_BYTES (128 * G2_LDA * 2)
#define G2_BBUF (128 * G2_LDB * 2)
#define G2_CN_OFF (G2_AS_BYTES + 2 * G2_BBUF)
#define G2_SMEM (G2_CN_OFF + 8192)

__global__ void __launch_bounds__(256) gemm2_kernel(float* __restrict__ out) {
    extern __shared__ char smem[];
    const uint32_t sb = smem_u32(smem);
    __half* As = (__half*)smem;
    float* cn_s = (float*)(smem + G2_CN_OFF);

    const int t = threadIdx.x;
    const int w = t >> 5, lane = t & 31;
    const int warpm = w >> 1, warpn = w & 1;
    const int g = lane >> 2, tig = lane & 3;
    const int j = lane >> 3, r = lane & 7;
    const int m0 = blockIdx.x * 128;

    #pragma unroll
    for (int i = 0; i < 8; ++i) cn_s[t + 256 * i] = g_cn[t + 256 * i];

    #pragma unroll
    for (int i = 0; i < 16; ++i) {
        int idx = t + 256 * i;
        int row = idx >> 5, q = idx & 31;
        uint4 v = *(const uint4*)(g_embh + (size_t)(m0 + row) * OUTC + q * 8);
        *(uint4*)(As + row * G2_LDA + q * 8) = v;
    }

    const uint32_t bs0 = sb + G2_AS_BYTES;

    const uint32_t abase = sb + ((warpm * 32 + (j & 1) * 8 + r) * G2_LDA + (j >> 1) * 8) * 2;
    const uint32_t bbase = bs0 + ((warpn * 64 + (j & 1) * 8 + r) * G2_LDB + (j >> 1) * 8) * 2;

    float t3[4][3];
    #pragma unroll
    for (int s = 0; s < 4; ++s) { t3[s][0] = 3.4e38f; t3[s][1] = 3.4e38f; t3[s][2] = 3.4e38f; }

    float acc[2][8][4];

    #pragma unroll
    for (int i = 0; i < 4; ++i) {
        int idx = t + 256 * i;
        int row = idx >> 3, q8 = (idx & 7) * 8;
        cp16(bs0 + (row * G2_LDB + q8) * 2, g_Ch + (size_t)row * OUTC + q8);
    }
    CP_COMMIT();
    __syncthreads();

    for (int gi = 0; gi < 64; ++gi) {
        int cur = gi & 1;
        int chunk = gi >> 2, sl = gi & 3;

        CP_WAIT0();
        __syncthreads();
        if (gi + 1 < 64) {
            int nchunk = (gi + 1) >> 2, nsl = (gi + 1) & 3;
            uint32_t bo = ((gi + 1) & 1) * G2_BBUF;
            #pragma unroll
            for (int i = 0; i < 4; ++i) {
                int idx = t + 256 * i;
                int row = idx >> 3, q8 = (idx & 7) * 8;
                cp16(bs0 + bo + (row * G2_LDB + q8) * 2,
                     g_Ch + (size_t)(nchunk * 128 + row) * OUTC + nsl * 64 + q8);
            }
            CP_COMMIT();
        }

        if (sl == 0) {
            #pragma unroll
            for (int mt = 0; mt < 2; ++mt)
                #pragma unroll
                for (int nt = 0; nt < 8; ++nt)
                    #pragma unroll
                    for (int q = 0; q < 4; ++q) acc[mt][nt][q] = 0.f;
        }

        uint32_t bbb = bbase + cur * G2_BBUF;
        #pragma unroll
        for (int ks = 0; ks < 4; ++ks) {
            int ks16 = ks * 16;
            int kk = sl * 64 + ks16;
            uint32_t a[2][4], bf[4][4];
            #pragma unroll
            for (int mt = 0; mt < 2; ++mt)
                ldsm4(a[mt], abase + (mt * 16 * G2_LDA + kk) * 2);
            #pragma unroll
            for (int ng = 0; ng < 4; ++ng)
                ldsm4(bf[ng], bbb + (ng * 16 * G2_LDB + ks16) * 2);
            #pragma unroll
            for (int mt = 0; mt < 2; ++mt)
                #pragma unroll
                for (int ng = 0; ng < 4; ++ng) {
                    mma16816(acc[mt][2*ng][0], acc[mt][2*ng][1], acc[mt][2*ng][2], acc[mt][2*ng][3],
                             a[mt][0], a[mt][1], a[mt][2], a[mt][3], bf[ng][0], bf[ng][2]);
                    mma16816(acc[mt][2*ng+1][0], acc[mt][2*ng+1][1], acc[mt][2*ng+1][2], acc[mt][2*ng+1][3],
                             a[mt][0], a[mt][1], a[mt][2], a[mt][3], bf[ng][1], bf[ng][3]);
                }
        }

        if (sl == 3) {
            #pragma unroll
            for (int mt = 0; mt < 2; ++mt) {
                #pragma unroll
                for (int nt = 0; nt < 8; ++nt) {
                    int col = chunk * 128 + warpn * 64 + nt * 8 + tig * 2;
                    float cn0 = cn_s[col], cn1 = cn_s[col + 1];
                    #pragma unroll
                    for (int hi = 0; hi < 2; ++hi) {
                        int s = mt * 2 + hi;
                        float v0 = cn0 - 2.f * acc[mt][nt][hi * 2 + 0];
                        float v1 = cn1 - 2.f * acc[mt][nt][hi * 2 + 1];
                        top3_insert(v0, t3[s][0], t3[s][1], t3[s][2]);
                        top3_insert(v1, t3[s][0], t3[s][1], t3[s][2]);
                    }
                }
            }
        }
    }
    __syncthreads();

    float* mrg = (float*)(smem + G2_AS_BYTES);
    #pragma unroll
    for (int mt = 0; mt < 2; ++mt)
        #pragma unroll
        for (int hi = 0; hi < 2; ++hi) {
            int row = warpm * 32 + mt * 16 + hi * 8 + g;
            int slot = warpn * 4 + tig;
            float* d = mrg + (row * 8 + slot) * 3;
            d[0] = t3[mt * 2 + hi][0];
            d[1] = t3[mt * 2 + hi][1];
            d[2] = t3[mt * 2 + hi][2];
        }
    __syncthreads();

    if (t < 128) {
        float b0 = 3.4e38f, b1 = 3.4e38f, b2 = 3.4e38f;
        const float* src = mrg + t * 24;
        #pragma unroll
        for (int q = 0; q < 24; ++q)
            top3_insert(src[q], b0, b1, b2);
        float en = g_en[m0 + t];
        float d0 = sqrtf(fmaxf(en + b0, 0.f));
        float d1 = sqrtf(fmaxf(en + b1, 0.f));
        float d2 = sqrtf(fmaxf(en + b2, 0.f));
        out[m0 + t] = d0 / (1.f + expf(d0 - d1) + expf(d0 - d2));
    }
}

// ============================================================
// Launcher
// ============================================================
extern "C" void kernel_launch(void* const* d_in, const int* in_sizes, int n_in,
                              void* d_out, int out_size) {
    const float* p1 = (const float*)d_in[0];
    const float* p2 = (const float*)d_in[1];
    const float* pw = (const float*)d_in[2];
    const float* pb = (const float*)d_in[3];
    const float* ce = (const float*)d_in[4];
    float* out = (float*)d_out;
    (void)in_sizes; (void)n_in; (void)out_size;

    cudaFuncSetAttribute(gemm1_kernel, cudaFuncAttributeMaxDynamicSharedMemorySize, G1_SMEM);
    cudaFuncSetAttribute(gemm2_kernel, cudaFuncAttributeMaxDynamicSharedMemorySize, G2_SMEM);

    pools_kernel<<<BB * C1 + BB * C2, 256>>>(p1, p2);
    conv_kernel<<<1536 + 256, 256>>>(pw, ce);
    gemm1_kernel<<<NPIX / 128, 256, G1_SMEM>>>(pb);
    gemm2_kernel<<<NPIX / 128, 256, G2_SMEM>>>(out);
}

// round 16
// speedup vs baseline: 1.0946x; 1.0031x over previous
#include <cuda_runtime.h>
#include <cuda_fp16.h>
#include <cstdint>

#define BB 16
#define C1 512
#define C2 1024
#define CTOT 1536
#define HW 4096
#define HW2 1024
#define OUTC 256
#define PP 2048
#define NPIX 65536

// ---------------- device scratch ----------------
__device__ __align__(16) __half g_pool[(size_t)BB * CTOT * HW];   // [b][c][hw]
__device__ __align__(16) __half g_Wh[OUTC * CTOT];                // [o][c]
__device__ __align__(16) __half g_Ch[PP * OUTC];                  // [p][c]
__device__ __align__(16) __half g_embh[(size_t)NPIX * OUTC];      // [pixel][o]
__device__ float g_en[NPIX];
__device__ float g_cn[PP];

// ---------------- asm helpers ----------------
__device__ __forceinline__ uint32_t smem_u32(const void* p) {
    uint32_t a;
    asm("{ .reg .u64 t; cvta.to.shared.u64 t, %1; cvt.u32.u64 %0, t; }" : "=r"(a) : "l"(p));
    return a;
}
__device__ __forceinline__ void mma16816(float& c0, float& c1, float& c2, float& c3,
                                         uint32_t a0, uint32_t a1, uint32_t a2, uint32_t a3,
                                         uint32_t b0, uint32_t b1) {
    asm volatile(
        "mma.sync.aligned.m16n8k16.row.col.f32.f16.f16.f32 "
        "{%0,%1,%2,%3}, {%4,%5,%6,%7}, {%8,%9}, {%0,%1,%2,%3};"
        : "+f"(c0), "+f"(c1), "+f"(c2), "+f"(c3)
        : "r"(a0), "r"(a1), "r"(a2), "r"(a3), "r"(b0), "r"(b1));
}
__device__ __forceinline__ void ldsm4(uint32_t* d, uint32_t addr) {
    asm volatile("ldmatrix.sync.aligned.m8n8.x4.shared.b16 {%0,%1,%2,%3}, [%4];"
                 : "=r"(d[0]), "=r"(d[1]), "=r"(d[2]), "=r"(d[3]) : "r"(addr));
}
__device__ __forceinline__ void ldsm4t(uint32_t* d, uint32_t addr) {
    asm volatile("ldmatrix.sync.aligned.m8n8.x4.trans.shared.b16 {%0,%1,%2,%3}, [%4];"
                 : "=r"(d[0]), "=r"(d[1]), "=r"(d[2]), "=r"(d[3]) : "r"(addr));
}
__device__ __forceinline__ void cp16(uint32_t dst, const void* src) {
    asm volatile("cp.async.cg.shared.global [%0], [%1], 16;" :: "r"(dst), "l"(src));
}
#define CP_COMMIT() asm volatile("cp.async.commit_group;" ::: "memory")
#define CP_WAIT0()  asm volatile("cp.async.wait_group 0;" ::: "memory")

// branch-free top-3 sorted insert (t0 <= t1 <= t2)
__device__ __forceinline__ void top3_insert(float v, float& t0, float& t1, float& t2) {
    float b0 = fmaxf(v, t0);
    t0 = fminf(v, t0);
    float b1 = fmaxf(b0, t1);
    t1 = fminf(b0, t1);
    t2 = fminf(b1, t2);
}

__device__ __forceinline__ void lin_taps(int i, int& j0, int& j1, float& w1) {
    float xf = 0.5f * (float)i - 0.25f;
    float fl = floorf(xf);
    int j = (int)fl;
    w1 = xf - fl;
    j0 = j < 0 ? 0 : j;
    j1 = (j + 1 > 31) ? 31 : (j + 1);
}

// ============================================================
// Kernel 1: fused pools, SEPARABLE 3x3, float4-vectorized.
// p1 blocks: 64x64 pool. p2 blocks: 32x32 pool + bilinear 32->64.
// ============================================================
__global__ void pools_kernel(const float* __restrict__ p1, const float* __restrict__ p2) {
    __shared__ __align__(16) float buf[3 * HW2 > 2 * HW ? 3 * HW2 : 2 * HW];  // 32 KB
    const float inv9 = 1.f / 9.f;
    int bid = blockIdx.x;
    int t = threadIdx.x;
    if (bid < BB * C1) {
        float4* s4 = (float4*)buf;              // [1024]
        float4* h4 = (float4*)(buf + HW);       // [1024]
        const float4* in4 = (const float4*)(p1 + (size_t)bid * HW);
        int b = bid / C1, c = bid - b * C1;
        __half* out = g_pool + ((size_t)b * CTOT + c) * HW;
        #pragma unroll
        for (int k = 0; k < 4; ++k) s4[t + 256 * k] = in4[t + 256 * k];
        __syncthreads();
        // horizontal pass (zero pad)
        const float* sf = (const float*)s4;
        #pragma unroll
        for (int k = 0; k < 4; ++k) {
            int i = t + 256 * k;
            int xq = i & 15;
            float4 cv = s4[i];
            float L = (xq > 0)  ? sf[4 * i - 1] : 0.f;
            float R = (xq < 15) ? sf[4 * i + 4] : 0.f;
            float4 hv;
            hv.x = L + cv.x + cv.y;
            hv.y = cv.x + cv.y + cv.z;
            hv.z = cv.y + cv.z + cv.w;
            hv.w = cv.z + cv.w + R;
            h4[i] = hv;
        }
        __syncthreads();
        // vertical pass + /9 + fp16 store
        #pragma unroll
        for (int k = 0; k < 4; ++k) {
            int i = t + 256 * k;
            int row = i >> 4;
            float4 cv = h4[i];
            if (row > 0)  { float4 u = h4[i - 16]; cv.x += u.x; cv.y += u.y; cv.z += u.z; cv.w += u.w; }
            if (row < 63) { float4 d = h4[i + 16]; cv.x += d.x; cv.y += d.y; cv.z += d.z; cv.w += d.w; }
            __half2 ha = __floats2half2_rn(cv.x * inv9, cv.y * inv9);
            __half2 hb = __floats2half2_rn(cv.z * inv9, cv.w * inv9);
            *(uint2*)(out + 4 * i) = make_uint2(*(uint32_t*)&ha, *(uint32_t*)&hb);
        }
    } else {
        int plane = bid - BB * C1;
        float4* s4 = (float4*)buf;                    // [256]
        float4* h4 = (float4*)(buf + HW2);            // [256]
        float*  q  = buf + 2 * HW2;                   // [1024]
        float4* q4 = (float4*)q;
        const float4* in4 = (const float4*)(p2 + (size_t)plane * HW2);
        int b = plane / C2, c = plane - b * C2;
        __half* out = g_pool + ((size_t)b * CTOT + C1 + c) * HW;
        s4[t] = in4[t];
        __syncthreads();
        {
            const float* sf = (const float*)s4;
            int xq = t & 7;
            float4 cv = s4[t];
            float L = (xq > 0) ? sf[4 * t - 1] : 0.f;
            float R = (xq < 7) ? sf[4 * t + 4] : 0.f;
            float4 hv;
            hv.x = L + cv.x + cv.y;
            hv.y = cv.x + cv.y + cv.z;
            hv.z = cv.y + cv.z + cv.w;
            hv.w = cv.z + cv.w + R;
            h4[t] = hv;
        }
        __syncthreads();
        {
            int row = t >> 3;
            float4 cv = h4[t];
            if (row > 0)  { float4 u = h4[t - 8]; cv.x += u.x; cv.y += u.y; cv.z += u.z; cv.w += u.w; }
            if (row < 31) { float4 d = h4[t + 8]; cv.x += d.x; cv.y += d.y; cv.z += d.z; cv.w += d.w; }
            cv.x *= inv9; cv.y *= inv9; cv.z *= inv9; cv.w *= inv9;
            q4[t] = cv;
        }
        __syncthreads();
        // bilinear 32->64: 512 groups of 8 out px; 2 iterations
        #pragma unroll
        for (int k = 0; k < 2; ++k) {
            int gidx = t + 256 * k;
            int y = gidx >> 3, xg = gidx & 7;
            int y0, y1; float wy;
            lin_taps(y, y0, y1, wy);
            float wyc = 1.f - wy;
            const float* r0 = q + y0 * 32 + xg * 4;
            const float* r1 = q + y1 * 32 + xg * 4;
            float4 a0 = *(const float4*)r0;
            float4 a1 = *(const float4*)r1;
            float l0 = (xg > 0) ? r0[-1] : a0.x;
            float l1 = (xg > 0) ? r1[-1] : a1.x;
            float rr0 = (xg < 7) ? r0[4] : a0.w;
            float rr1 = (xg < 7) ? r1[4] : a1.w;
            float e0[8], e1[8];
            e0[0] = 0.25f * l0  + 0.75f * a0.x;  e1[0] = 0.25f * l1  + 0.75f * a1.x;
            e0[1] = 0.75f * a0.x + 0.25f * a0.y; e1[1] = 0.75f * a1.x + 0.25f * a1.y;
            e0[2] = 0.25f * a0.x + 0.75f * a0.y; e1[2] = 0.25f * a1.x + 0.75f * a1.y;
            e0[3] = 0.75f * a0.y + 0.25f * a0.z; e1[3] = 0.75f * a1.y + 0.25f * a1.z;
            e0[4] = 0.25f * a0.y + 0.75f * a0.z; e1[4] = 0.25f * a1.y + 0.75f * a1.z;
            e0[5] = 0.75f * a0.z + 0.25f * a0.w; e1[5] = 0.75f * a1.z + 0.25f * a1.w;
            e0[6] = 0.25f * a0.z + 0.75f * a0.w; e1[6] = 0.25f * a1.z + 0.75f * a1.w;
            e0[7] = 0.75f * a0.w + 0.25f * rr0;  e1[7] = 0.75f * a1.w + 0.25f * rr1;
            uint32_t packed[4];
            #pragma unroll
            for (int p = 0; p < 4; ++p) {
                float o0 = e0[2 * p]     * wyc + e1[2 * p]     * wy;
                float o1 = e0[2 * p + 1] * wyc + e1[2 * p + 1] * wy;
                __half2 h = __floats2half2_rn(o0, o1);
                packed[p] = *(uint32_t*)&h;
            }
            *(uint4*)(out + y * 64 + xg * 8) = make_uint4(packed[0], packed[1], packed[2], packed[3]);
        }
    }
}

// ============================================================
// Kernel 2: fused conversions (W -> fp16; centroids -> fp16 + ||c||^2)
// ============================================================
__global__ void conv_kernel(const float* __restrict__ w, const float* __restrict__ cents) {
    int bid = blockIdx.x;
    if (bid < 1536) {
        int i = bid * 256 + threadIdx.x;
        g_Wh[i] = __float2half(w[i]);
    } else {
        int warp = (bid - 1536) * 8 + (threadIdx.x >> 5);
        int lane = threadIdx.x & 31;
        float s = 0.f;
        for (int k = lane; k < OUTC; k += 32) {
            __half h = __float2half(cents[(size_t)warp * OUTC + k]);
            g_Ch[(size_t)warp * OUTC + k] = h;
            float f = __half2float(h);
            s = fmaf(f, f, s);
        }
        #pragma unroll
        for (int off = 16; off; off >>= 1) s += __shfl_xor_sync(0xffffffffu, s, off);
        if (lane == 0) g_cn[warp] = s;
    }
}

// ============================================================
// Kernel 3: projection GEMM (R11/R14 config, unchanged).
// ============================================================
#define G1_LDA 136
#define G1_ABUF 17408
#define G1_LDB 72
#define G1_BBUF 36864
#define G1_BS_OFF 34816
#define G1_BIAS_OFF 108544
#define G1_EN_OFF 109568
#define G1_SMEM (G1_EN_OFF + 512)

__global__ void __launch_bounds__(256) gemm1_kernel(const float* __restrict__ bias) {
    extern __shared__ char smem[];
    const uint32_t sb = smem_u32(smem);
    float* bias_s = (float*)(smem + G1_BIAS_OFF);
    float* en_s = (float*)(smem + G1_EN_OFF);

    const int t = threadIdx.x;
    const int w = t >> 5, lane = t & 31;
    const int warpm = w >> 2, warpn = w & 3;
    const int g = lane >> 2, tig = lane & 3;
    const int j = lane >> 3, r = lane & 7;
    const int m0 = blockIdx.x * 128;
    const int b = m0 >> 12, hw0 = m0 & 4095;

    bias_s[t] = bias[t];
    if (t < 128) en_s[t] = 0.f;

    const int ak = t >> 4, am8 = (t & 15) * 8;
    const int bn = t >> 3, bkq8 = (t & 7) * 8;
    const __half* apsrc = g_pool + ((size_t)b * CTOT + ak) * HW + hw0 + am8;
    const __half* bpsrc = g_Wh + (size_t)bn * CTOT + bkq8;
    const uint32_t adst = sb + (ak * G1_LDA + am8) * 2;
    const uint32_t bdst = sb + G1_BS_OFF + (bn * G1_LDB + bkq8) * 2;

    const uint32_t abase = sb + (((j >> 1) * 8 + r) * G1_LDA + warpm * 64 + (j & 1) * 8) * 2;
    const uint32_t bbase = sb + G1_BS_OFF +
                           ((warpn * 64 + (j & 1) * 8 + r) * G1_LDB + (j >> 1) * 8) * 2;

    float acc[4][8][4];
    #pragma unroll
    for (int mt = 0; mt < 4; ++mt)
        #pragma unroll
        for (int nt = 0; nt < 8; ++nt)
            #pragma unroll
            for (int q = 0; q < 4; ++q) acc[mt][nt][q] = 0.f;

    #pragma unroll
    for (int i = 0; i < 4; ++i)
        cp16(adst + i * 16 * G1_LDA * 2, apsrc + (size_t)(16 * i) * HW);
    #pragma unroll
    for (int i = 0; i < 8; ++i)
        cp16(bdst + i * 32 * G1_LDB * 2, bpsrc + (size_t)(32 * i) * CTOT);
    CP_COMMIT();

    const int NT = CTOT / 64;  // 24
    for (int kt = 0; kt < NT; ++kt) {
        CP_WAIT0();
        __syncthreads();
        if (kt + 1 < NT) {
            int k0 = (kt + 1) * 64;
            uint32_t ao = ((kt + 1) & 1) * G1_ABUF;
            uint32_t bo = ((kt + 1) & 1) * G1_BBUF;
            #pragma unroll
            for (int i = 0; i < 4; ++i)
                cp16(adst + ao + i * 16 * G1_LDA * 2, apsrc + (size_t)(k0 + 16 * i) * HW);
            #pragma unroll
            for (int i = 0; i < 8; ++i)
                cp16(bdst + bo + i * 32 * G1_LDB * 2, bpsrc + (size_t)(32 * i) * CTOT + k0);
            CP_COMMIT();
        }
        uint32_t aab = abase + (kt & 1) * G1_ABUF;
        uint32_t bbb = bbase + (kt & 1) * G1_BBUF;
        #pragma unroll
        for (int ks = 0; ks < 4; ++ks) {
            int ks16 = ks * 16;
            uint32_t a[4][4], bf[4][4];
            #pragma unroll
            for (int mt = 0; mt < 4; ++mt)
                ldsm4t(a[mt], aab + (ks16 * G1_LDA + mt * 16) * 2);
            #pragma unroll
            for (int ng = 0; ng < 4; ++ng)
                ldsm4(bf[ng], bbb + (ng * 16 * G1_LDB + ks16) * 2);
            #pragma unroll
            for (int mt = 0; mt < 4; ++mt)
                #pragma unroll
                for (int ng = 0; ng < 4; ++ng) {
                    mma16816(acc[mt][2*ng][0], acc[mt][2*ng][1], acc[mt][2*ng][2], acc[mt][2*ng][3],
                             a[mt][0], a[mt][1], a[mt][2], a[mt][3], bf[ng][0], bf[ng][2]);
                    mma16816(acc[mt][2*ng+1][0], acc[mt][2*ng+1][1], acc[mt][2*ng+1][2], acc[mt][2*ng+1][3],
                             a[mt][0], a[mt][1], a[mt][2], a[mt][3], bf[ng][1], bf[ng][3]);
                }
        }
    }
    __syncthreads();

    #pragma unroll
    for (int mt = 0; mt < 4; ++mt) {
        int row0 = warpm * 64 + mt * 16 + g;
        float en0 = 0.f, en1 = 0.f;
        #pragma unroll
        for (int nt = 0; nt < 8; ++nt) {
            int col = warpn * 64 + nt * 8 + tig * 2;
            float f0 = acc[mt][nt][0] + bias_s[col];
            float f1 = acc[mt][nt][1] + bias_s[col + 1];
            __half2 h01 = __floats2half2_rn(f0, f1);
            *(uint32_t*)(g_embh + (size_t)(m0 + row0) * OUTC + col) = *(uint32_t*)&h01;
            float q0 = __half2float(__low2half(h01)), q1 = __half2float(__high2half(h01));
            en0 = fmaf(q0, q0, fmaf(q1, q1, en0));

            float f2 = acc[mt][nt][2] + bias_s[col];
            float f3 = acc[mt][nt][3] + bias_s[col + 1];
            __half2 h23 = __floats2half2_rn(f2, f3);
            *(uint32_t*)(g_embh + (size_t)(m0 + row0 + 8) * OUTC + col) = *(uint32_t*)&h23;
            float q2 = __half2float(__low2half(h23)), q3 = __half2float(__high2half(h23));
            en1 = fmaf(q2, q2, fmaf(q3, q3, en1));
        }
        en0 += __shfl_xor_sync(0xffffffffu, en0, 1);
        en0 += __shfl_xor_sync(0xffffffffu, en0, 2);
        en1 += __shfl_xor_sync(0xffffffffu, en1, 1);
        en1 += __shfl_xor_sync(0xffffffffu, en1, 2);
        if (tig == 0) {
            atomicAdd(&en_s[warpm * 64 + mt * 16 + g], en0);
            atomicAdd(&en_s[warpm * 64 + mt * 16 + 8 + g], en1);
        }
    }
    __syncthreads();
    if (t < 128) g_en[m0 + t] = en_s[t];
}

// ============================================================
// Kernel 4: distance GEMM + top-3 + score (R10/R14-best, unchanged).
// ============================================================
#define G2_LDA 264
#define G2_LDB 72
#define G2_AS_BYTES (128 * G2_LDA * 2)
#define G2_BBUF (128 * G2_LDB * 2)
#define G2_CN_OFF (G2_AS_BYTES + 2 * G2_BBUF)
#define G2_SMEM (G2_CN_OFF + 8192)

__global__ void __launch_bounds__(256) gemm2_kernel(float* __restrict__ out) {
    extern __shared__ char smem[];
    const uint32_t sb = smem_u32(smem);
    __half* As = (__half*)smem;
    float* cn_s = (float*)(smem + G2_CN_OFF);

    const int t = threadIdx.x;
    const int w = t >> 5, lane = t & 31;
    const int warpm = w >> 1, warpn = w & 1;
    const int g = lane >> 2, tig = lane & 3;
    const int j = lane >> 3, r = lane & 7;
    const int m0 = blockIdx.x * 128;

    #pragma unroll
    for (int i = 0; i < 8; ++i) cn_s[t + 256 * i] = g_cn[t + 256 * i];

    #pragma unroll
    for (int i = 0; i < 16; ++i) {
        int idx = t + 256 * i;
        int row = idx >> 5, q = idx & 31;
        uint4 v = *(const uint4*)(g_embh + (size_t)(m0 + row) * OUTC + q * 8);
        *(uint4*)(As + row * G2_LDA + q * 8) = v;
    }

    const uint32_t bs0 = sb + G2_AS_BYTES;

    const uint32_t abase = sb + ((warpm * 32 + (j & 1) * 8 + r) * G2_LDA + (j >> 1) * 8) * 2;
    const uint32_t bbase = bs0 + ((warpn * 64 + (j & 1) * 8 + r) * G2_LDB + (j >> 1) * 8) * 2;

    float t3[4][3];
    #pragma unroll
    for (int s = 0; s < 4; ++s) { t3[s][0] = 3.4e38f; t3[s][1] = 3.4e38f; t3[s][2] = 3.4e38f; }

    float acc[2][8][4];

    #pragma unroll
    for (int i = 0; i < 4; ++i) {
        int idx = t + 256 * i;
        int row = idx >> 3, q8 = (idx & 7) * 8;
        cp16(bs0 + (row * G2_LDB + q8) * 2, g_Ch + (size_t)row * OUTC + q8);
    }
    CP_COMMIT();
    __syncthreads();

    for (int gi = 0; gi < 64; ++gi) {
        int cur = gi & 1;
        int chunk = gi >> 2, sl = gi & 3;

        CP_WAIT0();
        __syncthreads();
        if (gi + 1 < 64) {
            int nchunk = (gi + 1) >> 2, nsl = (gi + 1) & 3;
            uint32_t bo = ((gi + 1) & 1) * G2_BBUF;
            #pragma unroll
            for (int i = 0; i < 4; ++i) {
                int idx = t + 256 * i;
                int row = idx >> 3, q8 = (idx & 7) * 8;
                cp16(bs0 + bo + (row * G2_LDB + q8) * 2,
                     g_Ch + (size_t)(nchunk * 128 + row) * OUTC + nsl * 64 + q8);
            }
            CP_COMMIT();
        }

        if (sl == 0) {
            #pragma unroll
            for (int mt = 0; mt < 2; ++mt)
                #pragma unroll
                for (int nt = 0; nt < 8; ++nt)
                    #pragma unroll
                    for (int q = 0; q < 4; ++q) acc[mt][nt][q] = 0.f;
        }

        uint32_t bbb = bbase + cur * G2_BBUF;
        #pragma unroll
        for (int ks = 0; ks < 4; ++ks) {
            int ks16 = ks * 16;
            int kk = sl * 64 + ks16;
            uint32_t a[2][4], bf[4][4];
            #pragma unroll
            for (int mt = 0; mt < 2; ++mt)
                ldsm4(a[mt], abase + (mt * 16 * G2_LDA + kk) * 2);
            #pragma unroll
            for (int ng = 0; ng < 4; ++ng)
                ldsm4(bf[ng], bbb + (ng * 16 * G2_LDB + ks16) * 2);
            #pragma unroll
            for (int mt = 0; mt < 2; ++mt)
                #pragma unroll
                for (int ng = 0; ng < 4; ++ng) {
                    mma16816(acc[mt][2*ng][0], acc[mt][2*ng][1], acc[mt][2*ng][2], acc[mt][2*ng][3],
                             a[mt][0], a[mt][1], a[mt][2], a[mt][3], bf[ng][0], bf[ng][2]);
                    mma16816(acc[mt][2*ng+1][0], acc[mt][2*ng+1][1], acc[mt][2*ng+1][2], acc[mt][2*ng+1][3],
                             a[mt][0], a[mt][1], a[mt][2], a[mt][3], bf[ng][1], bf[ng][3]);
                }
        }

        if (sl == 3) {
            #pragma unroll
            for (int mt = 0; mt < 2; ++mt) {
                #pragma unroll
                for (int nt = 0; nt < 8; ++nt) {
                    int col = chunk * 128 + warpn * 64 + nt * 8 + tig * 2;
                    float cn0 = cn_s[col], cn1 = cn_s[col + 1];
                    #pragma unroll
                    for (int hi = 0; hi < 2; ++hi) {
                        int s = mt * 2 + hi;
                        float v0 = cn0 - 2.f * acc[mt][nt][hi * 2 + 0];
                        float v1 = cn1 - 2.f * acc[mt][nt][hi * 2 + 1];
                        top3_insert(v0, t3[s][0], t3[s][1], t3[s][2]);
                        top3_insert(v1, t3[s][0], t3[s][1], t3[s][2]);
                    }
                }
            }
        }
    }
    __syncthreads();

    float* mrg = (float*)(smem + G2_AS_BYTES);
    #pragma unroll
    for (int mt = 0; mt < 2; ++mt)
        #pragma unroll
        for (int hi = 0; hi < 2; ++hi) {
            int row = warpm * 32 + mt * 16 + hi * 8 + g;
            int slot = warpn * 4 + tig;
            float* d = mrg + (row * 8 + slot) * 3;
            d[0] = t3[mt * 2 + hi][0];
            d[1] = t3[mt * 2 + hi][1];
            d[2] = t3[mt * 2 + hi][2];
        }
    __syncthreads();

    if (t < 128) {
        float b0 = 3.4e38f, b1 = 3.4e38f, b2 = 3.4e38f;
        const float* src = mrg + t * 24;
        #pragma unroll
        for (int q = 0; q < 24; ++q)
            top3_insert(src[q], b0, b1, b2);
        float en = g_en[m0 + t];
        float d0 = sqrtf(fmaxf(en + b0, 0.f));
        float d1 = sqrtf(fmaxf(en + b1, 0.f));
        float d2 = sqrtf(fmaxf(en + b2, 0.f));
        out[m0 + t] = d0 / (1.f + expf(d0 - d1) + expf(d0 - d2));
    }
}

// ============================================================
// Launcher
// ============================================================
extern "C" void kernel_launch(void* const* d_in, const int* in_sizes, int n_in,
                              void* d_out, int out_size) {
    const float* p1 = (const float*)d_in[0];
    const float* p2 = (const float*)d_in[1];
    const float* pw = (const float*)d_in[2];
    const float* pb = (const float*)d_in[3];
    const float* ce = (const float*)d_in[4];
    float* out = (float*)d_out;
    (void)in_sizes; (void)n_in; (void)out_size;

    cudaFuncSetAttribute(gemm1_kernel, cudaFuncAttributeMaxDynamicSharedMemorySize, G1_SMEM);
    cudaFuncSetAttribute(gemm2_kernel, cudaFuncAttributeMaxDynamicSharedMemorySize, G2_SMEM);

    pools_kernel<<<BB * C1 + BB * C2, 256>>>(p1, p2);
    conv_kernel<<<1536 + 256, 256>>>(pw, ce);
    gemm1_kernel<<<NPIX / 128, 256, G1_SMEM>>>(pb);
    gemm2_kernel<<<NPIX / 128, 256, G2_SMEM>>>(out);
}